// round 13
// baseline (speedup 1.0000x reference)
#include <cuda_runtime.h>
#include <cuda_bf16.h>
#include <cstdint>

#define Hd 512
#define Wd 512
#define HW (512*512)
#define Cc 64
#define Md 64
#define Ll 4

// ---------------- scratch (device globals) ----------------
__device__ float  d_v[Cc*HW];
__device__ float  d_s[Cc*HW];
__device__ float2 d_P[Hd*Cc*Md];       // [h][ch*64+n]
__device__ float2 d_G[Hd*Cc*Md];       // [h][ch*64+n]
__device__ float2 d_c[Md*Cc*Md];
__device__ float2 d_cp[4*Md*Cc*Md];
__device__ float2 d_dm[Md*Cc*Md];
__device__ uint32_t TFWH[32768], TFWL[32768];
__device__ uint32_t TIWH[32768], TIWL[32768];
__device__ uint32_t TFHAH[32768], TFHAL[32768];
__device__ uint32_t TIHAH[32768], TIHAL[32768];
__device__ uint2 WBF[4*2*2*1024];

__device__ __forceinline__ float gelu_f(float x){
    float y = 0.7978845608028654f*(x + 0.044715f*x*x*x);
    float e = __expf(2.0f*y);
    float t = 1.0f - __fdividef(2.0f, e + 1.0f);
    return 0.5f*x*(1.0f + t);
}

__device__ __forceinline__ uint32_t pack_bf16(float lo, float hi){
    uint32_t r;
    asm("cvt.rn.bf16x2.f32 %0, %1, %2;" : "=r"(r) : "f"(hi), "f"(lo));
    return r;
}
__device__ __forceinline__ uint32_t lo_residual(uint32_t hp, float f0, float f1){
    float l0 = f0 - __uint_as_float(hp << 16);
    float l1 = f1 - __uint_as_float(hp & 0xFFFF0000u);
    return pack_bf16(l0, l1);
}
__device__ __forceinline__ void mma16816(float* d,
        uint32_t a0, uint32_t a1, uint32_t a2, uint32_t a3,
        uint32_t b0, uint32_t b1){
    asm volatile(
        "mma.sync.aligned.m16n8k16.row.col.f32.bf16.bf16.f32 "
        "{%0,%1,%2,%3}, {%4,%5,%6,%7}, {%8,%9}, {%0,%1,%2,%3};"
        : "+f"(d[0]), "+f"(d[1]), "+f"(d[2]), "+f"(d[3])
        : "r"(a0), "r"(a1), "r"(a2), "r"(a3), "r"(b0), "r"(b1));
}
// cp.async helpers
__device__ __forceinline__ void cp_async16(uint32_t saddr, const void* g){
    asm volatile("cp.async.cg.shared.global [%0], [%1], 16;" :: "r"(saddr), "l"(g));
}
#define CP_COMMIT() asm volatile("cp.async.commit_group;" ::: "memory")
#define CP_WAIT0()  asm volatile("cp.async.wait_group 0;" ::: "memory")

// ---------------- tables ----------------
__global__ void k_tables(){
    int idx = blockIdx.x*256 + threadIdx.x;
    if (idx < 16384){
        int lane = idx & 31, nt = (idx >> 5) & 15;
        {
            int kt = (idx >> 9) & 3, c = idx >> 11;
            int col = nt*8 + (lane >> 2);
            int n = col >> 1, ri = col & 1;
            const float nrm = 1.0f/(float)(HW);
#pragma unroll
            for (int rr = 0; rr < 2; rr++){
                int k0 = c*64 + kt*16 + (lane & 3)*2 + rr*8;
                float s0, c0, s1, c1;
                sincospif((float)(n*k0)     * (1.0f/256.0f), &s0, &c0);
                sincospif((float)(n*(k0+1)) * (1.0f/256.0f), &s1, &c1);
                float f0 = (ri==0) ? c0*nrm : -s0*nrm;
                float f1 = (ri==0) ? c1*nrm : -s1*nrm;
                uint32_t hp = pack_bf16(f0, f1);
                TFWH[idx*2+rr] = hp;
                TFWL[idx*2+rr] = lo_residual(hp, f0, f1);
            }
        }
        {
            int kt = (idx >> 9) & 7, wt = idx >> 12;
            int w = wt*128 + nt*8 + (lane >> 2);
#pragma unroll
            for (int rr = 0; rr < 2; rr++){
                int k = kt*16 + (lane & 3)*2 + rr*8;
                int n = k >> 1;
                float a = (n==0) ? 1.0f : 2.0f;
                float s, c;
                sincospif((float)(n*w) * (1.0f/256.0f), &s, &c);
                float f0 =  a*c;
                float f1 = -a*s;
                uint32_t hp = pack_bf16(f0, f1);
                TIWH[idx*2+rr] = hp;
                TIWL[idx*2+rr] = lo_residual(hp, f0, f1);
            }
        }
    }
    {
        int reg = idx & 3, lane = (idx >> 2) & 31, ks = (idx >> 7) & 63, rg = (idx >> 13) & 3;
        int r = lane >> 2, q = lane & 3;
        int m  = rg*16 + r + (reg & 1)*8;
        int kb = ks*16 + 2*q + (reg >> 1)*8;
        int h  = kb >> 1;
        float s, c;
        sincospif((float)((m-32)*h) * (1.0f/256.0f), &s, &c);
        uint32_t hp = pack_bf16(c, s);
        TFHAH[idx] = hp;
        TFHAL[idx] = lo_residual(hp, c, s);
    }
    {
        int reg = idx & 3, lane = (idx >> 2) & 31, ks = (idx >> 7) & 7, rg = idx >> 10;
        int r = lane >> 2, q = lane & 3;
        int h  = rg*16 + r + (reg & 1)*8;
        int kb = ks*16 + 2*q + (reg >> 1)*8;
        int m  = kb >> 1;
        float s, c;
        sincospif((float)((m-32)*h) * (1.0f/256.0f), &s, &c);
        uint32_t hp = pack_bf16(c, s);
        TIHAH[idx] = hp;
        TIHAL[idx] = lo_residual(hp, c, s);
    }
}

// ---------------- residual-weight fragment tables ----------------
__global__ void k_wprep(const float* __restrict__ c1w, const float* __restrict__ c2w){
    int idx = blockIdx.x*256 + threadIdx.x;
    int lane = idx & 31;
    int kt   = (idx >> 5) & 3;
    int nt   = (idx >> 7) & 7;
    int mat  = (idx >> 10) & 1;
    int l    = idx >> 11;
    int r = lane >> 2, q = lane & 3;
    const float* W = (mat ? c2w : c1w) + l*4096;
    int n  = nt*8 + r;
    int k0 = kt*16 + 2*q;
    int k2 = k0 + 8;
    float f0 = W[n*64 + k0], f1 = W[n*64 + k0 + 1];
    float f2 = W[n*64 + k2], f3 = W[n*64 + k2 + 1];
    uint32_t h0 = pack_bf16(f0, f1), h1 = pack_bf16(f2, f3);
    uint32_t l0 = lo_residual(h0, f0, f1), l1 = lo_residual(h1, f2, f3);
    int fi = (nt*4 + kt)*32 + lane;
    WBF[((l*2 + mat)*2 + 0)*1024 + fi] = make_uint2(h0, h1);
    WBF[((l*2 + mat)*2 + 1)*1024 + fi] = make_uint2(l0, l1);
}

// ---------------- encoder ----------------
__global__ void k_enc(const float* __restrict__ u, const float* __restrict__ x,
                      const float* __restrict__ ew, const float* __restrict__ eb){
    int p  = blockIdx.x*256 + threadIdx.x;
    int ch = blockIdx.y;
    float w0 = ew[ch*3+0], w1 = ew[ch*3+1], w2 = ew[ch*3+2];
    d_v[(size_t)ch*HW + p] = w0*x[p] + w1*x[HW+p] + w2*u[p] + eb[ch];
}

// ================ forward W-DFT via mma.sync (cp.async double-buffered) ==========
// R10 compute shape: 64-row tiles, 128 threads = 4 m-warps, 16 n-tiles per warp.
__global__ void __launch_bounds__(128) k_fwdW(){
    __shared__ float Asm[2][64*64];        // 32 KB double buffer
    int ch = blockIdx.y, h0 = blockIdx.x*64;
    int tid = threadIdx.x;
    int lane = tid & 31, wid = tid >> 5;
    int q = lane & 3, r = lane >> 2;
    const float4* vb4 = (const float4*)(d_v + ((size_t)ch*Hd + h0)*Wd);

    int pr0 = wid*16 + r, pr1 = pr0 + 8;
    int sw0 = (pr0 & 7) << 3, sw1 = (pr1 & 7) << 3;

    // per-thread staging slots: 8 float4 per chunk
    uint32_t sbase[2];
    sbase[0] = (uint32_t)__cvta_generic_to_shared(&Asm[0][0]);
    sbase[1] = (uint32_t)__cvta_generic_to_shared(&Asm[1][0]);

    float acc[16][4];
#pragma unroll
    for (int nt=0; nt<16; nt++)
#pragma unroll
        for (int e=0; e<4; e++) acc[nt][e] = 0.f;

    // prologue: stage chunk 0 into buffer 0
#pragma unroll
    for (int t=0;t<8;t++){
        int idx = tid + t*128;             // 1024 = 64h x 16 w4
        int hl = idx >> 4, w4 = idx & 15;
        uint32_t dst = sbase[0] + (hl*64 + ((w4*4) ^ ((hl & 7) << 3)))*4;
        cp_async16(dst, vb4 + (size_t)hl*128 + w4);
    }
    CP_COMMIT();
    CP_WAIT0();
    __syncthreads();

    for (int c = 0; c < 8; c++){
        int cur = c & 1;
        if (c < 7){
            int nxt = cur ^ 1;
#pragma unroll
            for (int t=0;t<8;t++){
                int idx = tid + t*128;
                int hl = idx >> 4, w4 = idx & 15;
                uint32_t dst = sbase[nxt] + (hl*64 + ((w4*4) ^ ((hl & 7) << 3)))*4;
                cp_async16(dst, vb4 + (size_t)hl*128 + (c+1)*16 + w4);
            }
            CP_COMMIT();
        }
        const float* As = Asm[cur];
#pragma unroll
        for (int kt = 0; kt < 4; kt++){
            int i0 = kt*16 + 2*q, i1 = i0 + 8;
            float2 f0 = *(const float2*)&As[pr0*64 + (i0 ^ sw0)];
            float2 f1 = *(const float2*)&As[pr1*64 + (i0 ^ sw1)];
            float2 f2 = *(const float2*)&As[pr0*64 + (i1 ^ sw0)];
            float2 f3 = *(const float2*)&As[pr1*64 + (i1 ^ sw1)];
            uint32_t ah0 = pack_bf16(f0.x, f0.y), al0 = lo_residual(ah0, f0.x, f0.y);
            uint32_t ah1 = pack_bf16(f1.x, f1.y), al1 = lo_residual(ah1, f1.x, f1.y);
            uint32_t ah2 = pack_bf16(f2.x, f2.y), al2 = lo_residual(ah2, f2.x, f2.y);
            uint32_t ah3 = pack_bf16(f3.x, f3.y), al3 = lo_residual(ah3, f3.x, f3.y);
            int bbase = (c*4 + kt)*1024 + lane*2;
#pragma unroll
            for (int nt = 0; nt < 16; nt++){
                uint2 bh = *(const uint2*)&TFWH[bbase + nt*64];
                uint2 bl = *(const uint2*)&TFWL[bbase + nt*64];
                mma16816(acc[nt], ah0, ah1, ah2, ah3, bh.x, bh.y);
                mma16816(acc[nt], ah0, ah1, ah2, ah3, bl.x, bl.y);
                mma16816(acc[nt], al0, al1, al2, al3, bh.x, bh.y);
            }
        }
        if (c < 7){
            CP_WAIT0();
        }
        __syncthreads();
    }
#pragma unroll
    for (int nt = 0; nt < 16; nt++){
        int n = nt*4 + q;
        d_P[(size_t)(h0 + pr0)*4096 + ch*64 + n] = make_float2(acc[nt][0], acc[nt][1]);
        d_P[(size_t)(h0 + pr1)*4096 + ch*64 + n] = make_float2(acc[nt][2], acc[nt][3]);
    }
}

// ================ forward H-DFT via mma.sync, split-K x4 ================
__global__ void __launch_bounds__(128) k_fwdH(){
    __shared__ uint32_t BsmH[32*72], BsmL[32*72];
    int x0 = blockIdx.x*32, kp = blockIdx.y;
    int tid = threadIdx.x;
    int lane = tid & 31, wid = tid >> 5;
    int q = lane & 3, r = lane >> 2;

    float acc[8][4];
#pragma unroll
    for (int nt=0; nt<8; nt++)
#pragma unroll
        for (int e=0; e<4; e++) acc[nt][e] = 0.f;

#pragma unroll
    for (int c = 0; c < 4; c++){
        __syncthreads();
        int hbase = kp*128 + c*32;
#pragma unroll
        for (int k = 0; k < 8; k++){
            int idx = tid + k*128;
            int xl = idx & 31, hh = idx >> 5;
            float2 p = d_P[(size_t)(hbase+hh)*4096 + x0 + xl];
            uint32_t hre = pack_bf16(p.x,  p.y);
            uint32_t lre = lo_residual(hre, p.x,  p.y);
            uint32_t him = pack_bf16(p.y, -p.x);
            uint32_t lim = lo_residual(him, p.y, -p.x);
            *(uint2*)&BsmH[hh*72 + 2*xl] = make_uint2(hre, him);
            *(uint2*)&BsmL[hh*72 + 2*xl] = make_uint2(lre, lim);
        }
        __syncthreads();
#pragma unroll
        for (int kt = 0; kt < 4; kt++){
            int ks = kp*16 + c*4 + kt;
            uint4 ah = *(const uint4*)&TFHAH[((wid*64 + ks)*32 + lane)*4];
            uint4 al = *(const uint4*)&TFHAL[((wid*64 + ks)*32 + lane)*4];
#pragma unroll
            for (int nt = 0; nt < 8; nt++){
                int n = nt*8 + r;
                uint32_t b0h = BsmH[(kt*8+q  )*72 + n];
                uint32_t b1h = BsmH[(kt*8+q+4)*72 + n];
                uint32_t b0l = BsmL[(kt*8+q  )*72 + n];
                uint32_t b1l = BsmL[(kt*8+q+4)*72 + n];
                mma16816(acc[nt], ah.x, ah.y, ah.z, ah.w, b0h, b1h);
                mma16816(acc[nt], ah.x, ah.y, ah.z, ah.w, b0l, b1l);
                mma16816(acc[nt], al.x, al.y, al.z, al.w, b0h, b1h);
            }
        }
    }
    int m0 = wid*16 + r;
    float2* cp = d_cp + (size_t)kp*(Md*Cc*Md);
#pragma unroll
    for (int nt = 0; nt < 8; nt++){
        int x = x0 + nt*4 + q;
        cp[(size_t)m0*4096 + x]     = make_float2(acc[nt][0], acc[nt][1]);
        cp[(size_t)(m0+8)*4096 + x] = make_float2(acc[nt][2], acc[nt][3]);
    }
}

// ---------------- reduce split-K partials ----------------
__global__ void k_cred(){
    int p = blockIdx.x*256 + threadIdx.x;
    const int S = Md*Cc*Md;
    float2 a = d_cp[p], b = d_cp[S+p], c = d_cp[2*S+p], d = d_cp[3*S+p];
    d_c[p] = make_float2(a.x+b.x+c.x+d.x, a.y+b.y+c.y+d.y);
}

// ---------------- per-mode channel mixing ----------------
__global__ void k_mix(const float* __restrict__ Ar, const float* __restrict__ Ai){
    int o  = blockIdx.y;
    int t2 = blockIdx.x*256 + threadIdx.x;
    int mode = t2*2;
    int m = mode >> 6, n = mode & 63;
    const float2* arp = (const float2*)(Ar + (size_t)o*Cc*4096 + mode);
    const float2* aip = (const float2*)(Ai + (size_t)o*Cc*4096 + mode);
    const float4* cp  = (const float4*)(d_c + ((size_t)m << 12) + n);
    float dr0=0.f, di0=0.f, dr1=0.f, di1=0.f;
#pragma unroll 8
    for (int i=0; i<Cc; i++){
        float2 a = __ldg(arp + (size_t)i*2048);
        float2 b = __ldg(aip + (size_t)i*2048);
        float4 cc = cp[i*32];
        dr0 += a.x*cc.x - b.x*cc.y;  di0 += a.x*cc.y + b.x*cc.x;
        dr1 += a.y*cc.z - b.y*cc.w;  di1 += a.y*cc.w + b.y*cc.z;
    }
    *(float4*)(d_dm + ((size_t)m << 12) + (o << 6) + n) = make_float4(dr0, di0, dr1, di1);
}

// ================ inverse H-DFT via mma.sync ================
__global__ void __launch_bounds__(128) k_invH(){
    __shared__ uint32_t BsmH[64*72], BsmL[64*72];
    int x0 = blockIdx.x*32, h0 = blockIdx.y*64;
    int tid = threadIdx.x;
    int lane = tid & 31, wid = tid >> 5;
    int q = lane & 3, r = lane >> 2;

#pragma unroll
    for (int k = 0; k < 16; k++){
        int idx = tid + k*128;
        int xl = idx & 31, m = idx >> 5;
        float2 p = d_dm[(size_t)m*4096 + x0 + xl];
        uint32_t hre = pack_bf16(p.x, -p.y);
        uint32_t lre = lo_residual(hre, p.x, -p.y);
        uint32_t him = pack_bf16(p.y,  p.x);
        uint32_t lim = lo_residual(him, p.y,  p.x);
        *(uint2*)&BsmH[m*72 + 2*xl] = make_uint2(hre, him);
        *(uint2*)&BsmL[m*72 + 2*xl] = make_uint2(lre, lim);
    }
    __syncthreads();

    float acc[8][4];
#pragma unroll
    for (int nt=0; nt<8; nt++)
#pragma unroll
        for (int e=0; e<4; e++) acc[nt][e] = 0.f;

    int rg = blockIdx.y*4 + wid;
#pragma unroll
    for (int ks = 0; ks < 8; ks++){
        uint4 ah = *(const uint4*)&TIHAH[((rg*8 + ks)*32 + lane)*4];
        uint4 al = *(const uint4*)&TIHAL[((rg*8 + ks)*32 + lane)*4];
#pragma unroll
        for (int nt = 0; nt < 8; nt++){
            int n = nt*8 + r;
            uint32_t b0h = BsmH[(ks*8+q  )*72 + n];
            uint32_t b1h = BsmH[(ks*8+q+4)*72 + n];
            uint32_t b0l = BsmL[(ks*8+q  )*72 + n];
            uint32_t b1l = BsmL[(ks*8+q+4)*72 + n];
            mma16816(acc[nt], ah.x, ah.y, ah.z, ah.w, b0h, b1h);
            mma16816(acc[nt], ah.x, ah.y, ah.z, ah.w, b0l, b1l);
            mma16816(acc[nt], al.x, al.y, al.z, al.w, b0h, b1h);
        }
    }
    int hrow = h0 + wid*16 + r;
#pragma unroll
    for (int nt = 0; nt < 8; nt++){
        int x = x0 + nt*4 + q;
        d_G[(size_t)hrow*4096 + x]     = make_float2(acc[nt][0], acc[nt][1]);
        d_G[(size_t)(hrow+8)*4096 + x] = make_float2(acc[nt][2], acc[nt][3]);
    }
}

// ================ inverse W-DFT via mma.sync (cp.async staged) ================
__global__ void __launch_bounds__(128) k_invW(){
    __shared__ float Asm[64*128];
    int ch = blockIdx.y;
    int h0 = (blockIdx.x >> 2)*64;
    int wt = blockIdx.x & 3;
    int tid = threadIdx.x;
    int lane = tid & 31, wid = tid >> 5;
    int q = lane & 3, r = lane >> 2;
    const float4* Gf4 = (const float4*)d_G;

    int pr0 = wid*16 + r, pr1 = pr0 + 8;
    int sw0 = (pr0 & 7) << 3, sw1 = (pr1 & 7) << 3;

    uint32_t sbase = (uint32_t)__cvta_generic_to_shared(Asm);
#pragma unroll
    for (int t = 0; t < 16; t++){
        int idx = tid + t*128;             // 2048 = 64h x 32 c4
        int hl = idx >> 5, c4 = idx & 31;
        uint32_t dst = sbase + (hl*128 + ((c4*4) ^ ((hl & 7) << 3)))*4;
        cp_async16(dst, Gf4 + (size_t)(h0+hl)*2048 + ch*32 + c4);
    }
    CP_COMMIT();
    CP_WAIT0();
    __syncthreads();

    float acc[16][4];
#pragma unroll
    for (int nt=0; nt<16; nt++)
#pragma unroll
        for (int e=0; e<4; e++) acc[nt][e] = 0.f;

#pragma unroll
    for (int kt = 0; kt < 8; kt++){
        int i0 = kt*16 + 2*q, i1 = i0 + 8;
        float2 f0 = *(const float2*)&Asm[pr0*128 + (i0 ^ sw0)];
        float2 f1 = *(const float2*)&Asm[pr1*128 + (i0 ^ sw1)];
        float2 f2 = *(const float2*)&Asm[pr0*128 + (i1 ^ sw0)];
        float2 f3 = *(const float2*)&Asm[pr1*128 + (i1 ^ sw1)];
        uint32_t ah0 = pack_bf16(f0.x, f0.y), al0 = lo_residual(ah0, f0.x, f0.y);
        uint32_t ah1 = pack_bf16(f1.x, f1.y), al1 = lo_residual(ah1, f1.x, f1.y);
        uint32_t ah2 = pack_bf16(f2.x, f2.y), al2 = lo_residual(ah2, f2.x, f2.y);
        uint32_t ah3 = pack_bf16(f3.x, f3.y), al3 = lo_residual(ah3, f3.x, f3.y);
        int bbase = (wt*8 + kt)*1024 + lane*2;
#pragma unroll
        for (int nt = 0; nt < 16; nt++){
            uint2 bh = *(const uint2*)&TIWH[bbase + nt*64];
            uint2 bl = *(const uint2*)&TIWL[bbase + nt*64];
            mma16816(acc[nt], ah0, ah1, ah2, ah3, bh.x, bh.y);
            mma16816(acc[nt], ah0, ah1, ah2, ah3, bl.x, bl.y);
            mma16816(acc[nt], al0, al1, al2, al3, bh.x, bh.y);
        }
    }
#pragma unroll
    for (int nt = 0; nt < 16; nt++){
        int w = wt*128 + nt*8 + 2*q;
        *(float2*)&d_s[((size_t)ch*Hd + h0 + pr0)*Wd + w] = make_float2(acc[nt][0], acc[nt][1]);
        *(float2*)&d_s[((size_t)ch*Hd + h0 + pr1)*Wd + w] = make_float2(acc[nt][2], acc[nt][3]);
    }
}

// ================= mma.sync bf16 fused residual block v2 =================
#define RT2 2
__global__ void __launch_bounds__(256) k_resid_mma(
        int l,
        const float* __restrict__ b1, const float* __restrict__ b2,
        const float* __restrict__ dw, const float* __restrict__ db,
        float* __restrict__ dout){
    __shared__ float Asm[128*64];

    int tid  = threadIdx.x;
    int lane = tid & 31, wid = tid >> 5;
    int q = lane & 3, r = lane >> 2;

    const uint2* w1h = WBF + ((l*2 + 0)*2 + 0)*1024;
    const uint2* w1l = WBF + ((l*2 + 0)*2 + 1)*1024;
    const uint2* w2h = WBF + ((l*2 + 1)*2 + 0)*1024;
    const uint2* w2l = WBF + ((l*2 + 1)*2 + 1)*1024;

    int wpx = wid * 16;
    int pr0 = wpx + r, pr1 = pr0 + 8;
    int sw0 = (pr0 & 7) << 3, sw1 = (pr1 & 7) << 3;
    float db0 = (dout != nullptr) ? __ldg(db) : 0.f;

    for (int t = 0; t < RT2; t++){
        size_t pbase = ((size_t)blockIdx.x*RT2 + t)*128;
        __syncthreads();
#pragma unroll 8
        for (int c = 0; c < 32; c++){
            int idx = tid + c*256;
            int i = idx >> 7, px = idx & 127;
            Asm[px*64 + (i ^ ((px & 7) << 3))] = d_s[(size_t)i*HW + pbase + px];
        }
        __syncthreads();

        float acc1[8][4];
#pragma unroll
        for (int nt=0; nt<8; nt++)
#pragma unroll
            for (int e=0; e<4; e++) acc1[nt][e] = 0.f;

#pragma unroll
        for (int kt = 0; kt < 4; kt++){
            int i0 = kt*16 + 2*q, i1 = i0 + 8;
            float2 f0 = *(const float2*)&Asm[pr0*64 + (i0 ^ sw0)];
            float2 f1 = *(const float2*)&Asm[pr1*64 + (i0 ^ sw1)];
            float2 f2 = *(const float2*)&Asm[pr0*64 + (i1 ^ sw0)];
            float2 f3 = *(const float2*)&Asm[pr1*64 + (i1 ^ sw1)];
            uint32_t ah0 = pack_bf16(f0.x, f0.y), al0 = lo_residual(ah0, f0.x, f0.y);
            uint32_t ah1 = pack_bf16(f1.x, f1.y), al1 = lo_residual(ah1, f1.x, f1.y);
            uint32_t ah2 = pack_bf16(f2.x, f2.y), al2 = lo_residual(ah2, f2.x, f2.y);
            uint32_t ah3 = pack_bf16(f3.x, f3.y), al3 = lo_residual(ah3, f3.x, f3.y);
#pragma unroll
            for (int nt = 0; nt < 8; nt++){
                int fi = (nt*4 + kt)*32 + lane;
                uint2 bh = __ldg(w1h + fi);
                uint2 bl = __ldg(w1l + fi);
                mma16816(acc1[nt], ah0, ah1, ah2, ah3, bh.x, bh.y);
                mma16816(acc1[nt], ah0, ah1, ah2, ah3, bl.x, bl.y);
                mma16816(acc1[nt], al0, al1, al2, al3, bh.x, bh.y);
            }
        }

        uint32_t a2h[4][4], a2l[4][4];
#pragma unroll
        for (int nt = 0; nt < 8; nt++){
            int j0 = nt*8 + 2*q;
            float bj0 = __ldg(b1 + j0), bj1 = __ldg(b1 + j0 + 1);
            float g0 = gelu_f(acc1[nt][0] + bj0);
            float g1 = gelu_f(acc1[nt][1] + bj1);
            float g2 = gelu_f(acc1[nt][2] + bj0);
            float g3 = gelu_f(acc1[nt][3] + bj1);
            uint32_t h01 = pack_bf16(g0, g1), l01 = lo_residual(h01, g0, g1);
            uint32_t h23 = pack_bf16(g2, g3), l23 = lo_residual(h23, g2, g3);
            int kt = nt >> 1;
            if ((nt & 1) == 0){
                a2h[kt][0] = h01; a2h[kt][1] = h23;
                a2l[kt][0] = l01; a2l[kt][1] = l23;
            } else {
                a2h[kt][2] = h01; a2h[kt][3] = h23;
                a2l[kt][2] = l01; a2l[kt][3] = l23;
            }
        }

        float acc2[8][4];
#pragma unroll
        for (int nt=0; nt<8; nt++)
#pragma unroll
            for (int e=0; e<4; e++) acc2[nt][e] = 0.f;
#pragma unroll
        for (int kt = 0; kt < 4; kt++){
#pragma unroll
            for (int nt = 0; nt < 8; nt++){
                int fi = (nt*4 + kt)*32 + lane;
                uint2 bh = __ldg(w2h + fi);
                uint2 bl = __ldg(w2l + fi);
                mma16816(acc2[nt], a2h[kt][0], a2h[kt][1], a2h[kt][2], a2h[kt][3], bh.x, bh.y);
                mma16816(acc2[nt], a2h[kt][0], a2h[kt][1], a2h[kt][2], a2h[kt][3], bl.x, bl.y);
                mma16816(acc2[nt], a2l[kt][0], a2l[kt][1], a2l[kt][2], a2l[kt][3], bh.x, bh.y);
            }
        }

        size_t p0 = pbase + wpx + r, p1 = p0 + 8;
        float sum0 = 0.f, sum1 = 0.f;
#pragma unroll
        for (int nt = 0; nt < 8; nt++){
            int ch0 = nt*8 + 2*q, ch1 = ch0 + 1;
            float bb0 = __ldg(b2 + ch0), bb1 = __ldg(b2 + ch1);
            float v00 = d_v[(size_t)ch0*HW + p0] + gelu_f(acc2[nt][0] + bb0);
            float v10 = d_v[(size_t)ch1*HW + p0] + gelu_f(acc2[nt][1] + bb1);
            float v01 = d_v[(size_t)ch0*HW + p1] + gelu_f(acc2[nt][2] + bb0);
            float v11 = d_v[(size_t)ch1*HW + p1] + gelu_f(acc2[nt][3] + bb1);
            if (dout == nullptr){
                d_v[(size_t)ch0*HW + p0] = v00;
                d_v[(size_t)ch1*HW + p0] = v10;
                d_v[(size_t)ch0*HW + p1] = v01;
                d_v[(size_t)ch1*HW + p1] = v11;
            } else {
                float w0 = __ldg(dw + ch0), w1 = __ldg(dw + ch1);
                sum0 += w0*v00 + w1*v10;
                sum1 += w0*v01 + w1*v11;
            }
        }
        if (dout != nullptr){
            sum0 += __shfl_xor_sync(0xffffffffu, sum0, 1);
            sum0 += __shfl_xor_sync(0xffffffffu, sum0, 2);
            sum1 += __shfl_xor_sync(0xffffffffu, sum1, 1);
            sum1 += __shfl_xor_sync(0xffffffffu, sum1, 2);
            if (q == 0){
                dout[p0] = sum0 + db0;
                dout[p1] = sum1 + db0;
            }
        }
    }
}

// ---------------- launch ----------------
extern "C" void kernel_launch(void* const* d_in, const int* in_sizes, int n_in,
                              void* d_out, int out_size){
    const float* u    = (const float*)d_in[0];
    const float* x    = (const float*)d_in[1];
    const float* encw = (const float*)d_in[2];
    const float* encb = (const float*)d_in[3];
    const float* decw = (const float*)d_in[4];
    const float* decb = (const float*)d_in[5];
    const float* c1w  = (const float*)d_in[6];
    const float* c1b  = (const float*)d_in[7];
    const float* c2w  = (const float*)d_in[8];
    const float* c2b  = (const float*)d_in[9];
    const float* Are  = (const float*)d_in[10];
    const float* Aim  = (const float*)d_in[11];
    float* out = (float*)d_out;

    k_tables<<<128, 256>>>();
    k_wprep<<<32, 256>>>(c1w, c2w);
    k_enc<<<dim3(HW/256, Cc), 256>>>(u, x, encw, encb);

    for (int l=0; l<Ll; l++){
        k_fwdW<<<dim3(8, Cc), 128>>>();
        k_fwdH<<<dim3(128, 4), 128>>>();
        k_cred<<<1024, 256>>>();
        k_mix<<<dim3(8, Cc), 256>>>(Are + (size_t)l*Cc*Cc*4096,
                                    Aim + (size_t)l*Cc*Cc*4096);
        k_invH<<<dim3(128, 8), 128>>>();
        k_invW<<<dim3(32, Cc), 128>>>();
        bool last = (l == Ll-1);
        k_resid_mma<<<HW/(128*RT2), 256>>>(l, c1b + l*64, c2b + l*64,
                                           last ? decw : nullptr,
                                           last ? decb : nullptr,
                                           last ? out  : nullptr);
    }
}

// round 14
// speedup vs baseline: 1.2590x; 1.2590x over previous
#include <cuda_runtime.h>
#include <cuda_bf16.h>
#include <cstdint>

#define Hd 512
#define Wd 512
#define HW (512*512)
#define Cc 64
#define Md 64
#define Ll 4

// ---------------- scratch (device globals) ----------------
__device__ float  d_v[Cc*HW];
__device__ float  d_s[Cc*HW];
__device__ float2 d_P[Hd*Cc*Md];       // [h][ch*64+n]
__device__ float2 d_G[Hd*Cc*Md];       // [h][ch*64+n]
__device__ float2 d_c[Md*Cc*Md];
__device__ float2 d_cp[4*Md*Cc*Md];
__device__ float2 d_dm[Md*Cc*Md];
// fwdW folded B-frag table: idx=(((c*2+kt)*2+p)*8+nt)*32+lane, elems idx*2+rr (8192*2 used)
__device__ uint32_t TFWH[32768], TFWL[32768];
__device__ uint32_t TIWH[32768], TIWL[32768];
__device__ uint32_t TFHAH[32768], TFHAL[32768];
__device__ uint32_t TIHAH[32768], TIHAL[32768];
__device__ uint2 WBF[4*2*2*1024];

__device__ __forceinline__ float gelu_f(float x){
    float y = 0.7978845608028654f*(x + 0.044715f*x*x*x);
    float e = __expf(2.0f*y);
    float t = 1.0f - __fdividef(2.0f, e + 1.0f);
    return 0.5f*x*(1.0f + t);
}

__device__ __forceinline__ uint32_t pack_bf16(float lo, float hi){
    uint32_t r;
    asm("cvt.rn.bf16x2.f32 %0, %1, %2;" : "=r"(r) : "f"(hi), "f"(lo));
    return r;
}
__device__ __forceinline__ uint32_t lo_residual(uint32_t hp, float f0, float f1){
    float l0 = f0 - __uint_as_float(hp << 16);
    float l1 = f1 - __uint_as_float(hp & 0xFFFF0000u);
    return pack_bf16(l0, l1);
}
__device__ __forceinline__ void mma16816(float* d,
        uint32_t a0, uint32_t a1, uint32_t a2, uint32_t a3,
        uint32_t b0, uint32_t b1){
    asm volatile(
        "mma.sync.aligned.m16n8k16.row.col.f32.bf16.bf16.f32 "
        "{%0,%1,%2,%3}, {%4,%5,%6,%7}, {%8,%9}, {%0,%1,%2,%3};"
        : "+f"(d[0]), "+f"(d[1]), "+f"(d[2]), "+f"(d[3])
        : "r"(a0), "r"(a1), "r"(a2), "r"(a3), "r"(b0), "r"(b1));
}

// ---------------- tables ----------------
__global__ void k_tables(){
    int idx = blockIdx.x*256 + threadIdx.x;
    // folded fwdW B frags (even/odd parity over K=256)
    if (idx < 8192){
        int lane = idx & 31;
        int nt = (idx >> 5) & 7;
        int p  = (idx >> 8) & 1;
        int kt = (idx >> 9) & 1;
        int c  = (idx >> 10) & 7;
        int col = nt*8 + (lane >> 2);
        int posc = col >> 1, ri = col & 1;
        int n = 2*posc + p;
        const float nrm = 1.0f/(float)(HW);
#pragma unroll
        for (int rr = 0; rr < 2; rr++){
            int wk = c*32 + kt*16 + (lane & 3)*2 + rr*8;
            float s0, c0, s1, c1;
            sincospif((float)(n*wk)     * (1.0f/256.0f), &s0, &c0);
            sincospif((float)(n*(wk+1)) * (1.0f/256.0f), &s1, &c1);
            float f0 = (ri==0) ? c0*nrm : -s0*nrm;
            float f1 = (ri==0) ? c1*nrm : -s1*nrm;
            uint32_t hp = pack_bf16(f0, f1);
            TFWH[idx*2+rr] = hp;
            TFWL[idx*2+rr] = lo_residual(hp, f0, f1);
        }
    }
    if (idx < 16384){
        int lane = idx & 31, nt = (idx >> 5) & 15;
        int kt = (idx >> 9) & 7, wt = idx >> 12;
        int w = wt*128 + nt*8 + (lane >> 2);
#pragma unroll
        for (int rr = 0; rr < 2; rr++){
            int k = kt*16 + (lane & 3)*2 + rr*8;
            int n = k >> 1;
            float a = (n==0) ? 1.0f : 2.0f;
            float s, c;
            sincospif((float)(n*w) * (1.0f/256.0f), &s, &c);
            float f0 =  a*c;
            float f1 = -a*s;
            uint32_t hp = pack_bf16(f0, f1);
            TIWH[idx*2+rr] = hp;
            TIWL[idx*2+rr] = lo_residual(hp, f0, f1);
        }
    }
    {
        int reg = idx & 3, lane = (idx >> 2) & 31, ks = (idx >> 7) & 63, rg = (idx >> 13) & 3;
        int r = lane >> 2, q = lane & 3;
        int m  = rg*16 + r + (reg & 1)*8;
        int kb = ks*16 + 2*q + (reg >> 1)*8;
        int h  = kb >> 1;
        float s, c;
        sincospif((float)((m-32)*h) * (1.0f/256.0f), &s, &c);
        uint32_t hp = pack_bf16(c, s);
        TFHAH[idx] = hp;
        TFHAL[idx] = lo_residual(hp, c, s);
    }
    {
        int reg = idx & 3, lane = (idx >> 2) & 31, ks = (idx >> 7) & 7, rg = idx >> 10;
        int r = lane >> 2, q = lane & 3;
        int h  = rg*16 + r + (reg & 1)*8;
        int kb = ks*16 + 2*q + (reg >> 1)*8;
        int m  = kb >> 1;
        float s, c;
        sincospif((float)((m-32)*h) * (1.0f/256.0f), &s, &c);
        uint32_t hp = pack_bf16(c, s);
        TIHAH[idx] = hp;
        TIHAL[idx] = lo_residual(hp, c, s);
    }
}

// ---------------- residual-weight fragment tables ----------------
__global__ void k_wprep(const float* __restrict__ c1w, const float* __restrict__ c2w){
    int idx = blockIdx.x*256 + threadIdx.x;
    int lane = idx & 31;
    int kt   = (idx >> 5) & 3;
    int nt   = (idx >> 7) & 7;
    int mat  = (idx >> 10) & 1;
    int l    = idx >> 11;
    int r = lane >> 2, q = lane & 3;
    const float* W = (mat ? c2w : c1w) + l*4096;
    int n  = nt*8 + r;
    int k0 = kt*16 + 2*q;
    int k2 = k0 + 8;
    float f0 = W[n*64 + k0], f1 = W[n*64 + k0 + 1];
    float f2 = W[n*64 + k2], f3 = W[n*64 + k2 + 1];
    uint32_t h0 = pack_bf16(f0, f1), h1 = pack_bf16(f2, f3);
    uint32_t l0 = lo_residual(h0, f0, f1), l1 = lo_residual(h1, f2, f3);
    int fi = (nt*4 + kt)*32 + lane;
    WBF[((l*2 + mat)*2 + 0)*1024 + fi] = make_uint2(h0, h1);
    WBF[((l*2 + mat)*2 + 1)*1024 + fi] = make_uint2(l0, l1);
}

// ---------------- encoder ----------------
__global__ void k_enc(const float* __restrict__ u, const float* __restrict__ x,
                      const float* __restrict__ ew, const float* __restrict__ eb){
    int p  = blockIdx.x*256 + threadIdx.x;
    int ch = blockIdx.y;
    float w0 = ew[ch*3+0], w1 = ew[ch*3+1], w2 = ew[ch*3+2];
    d_v[(size_t)ch*HW + p] = w0*x[p] + w1*x[HW+p] + w2*u[p] + eb[ch];
}

// ================ forward W-DFT via mma.sync (even/odd folded, K=256) ================
// R10 schedule: 64-row tiles, 128 threads = 4 m-warps; per warp 8 even + 8 odd n-tiles.
__global__ void __launch_bounds__(128) k_fwdW(){
    __shared__ float Asm[64*64];           // a in logical cols 0-31, b in 32-63 (swizzled)
    int ch = blockIdx.y, h0 = blockIdx.x*64;
    int tid = threadIdx.x;
    int lane = tid & 31, wid = tid >> 5;
    int q = lane & 3, r = lane >> 2;
    const float4* vb4 = (const float4*)(d_v + ((size_t)ch*Hd + h0)*Wd);

    int pr0 = wid*16 + r, pr1 = pr0 + 8;
    int sw0 = (pr0 & 7) << 3, sw1 = (pr1 & 7) << 3;

    float accE[8][4], accO[8][4];
#pragma unroll
    for (int nt=0; nt<8; nt++)
#pragma unroll
        for (int e=0; e<4; e++){ accE[nt][e] = 0.f; accO[nt][e] = 0.f; }

    float4 lo[4], hi[4];
#pragma unroll
    for (int t=0;t<4;t++){
        int slot = tid + t*128;            // 512 = 64h x 8w4
        int hl = slot >> 3, w4 = slot & 7;
        lo[t] = vb4[(size_t)hl*128 + w4];
        hi[t] = vb4[(size_t)hl*128 + 64 + w4];
    }

    for (int c = 0; c < 8; c++){
        __syncthreads();
#pragma unroll
        for (int t=0;t<4;t++){
            int slot = tid + t*128;
            int hl = slot >> 3, w4 = slot & 7;
            float4 av, bv;
            av.x = lo[t].x + hi[t].x;  bv.x = lo[t].x - hi[t].x;
            av.y = lo[t].y + hi[t].y;  bv.y = lo[t].y - hi[t].y;
            av.z = lo[t].z + hi[t].z;  bv.z = lo[t].z - hi[t].z;
            av.w = lo[t].w + hi[t].w;  bv.w = lo[t].w - hi[t].w;
            int sw = (hl & 7) << 3;
            *(float4*)&Asm[hl*64 + ((w4*4) ^ sw)]      = av;
            *(float4*)&Asm[hl*64 + ((32 + w4*4) ^ sw)] = bv;
        }
        __syncthreads();
        if (c < 7){
#pragma unroll
            for (int t=0;t<4;t++){
                int slot = tid + t*128;
                int hl = slot >> 3, w4 = slot & 7;
                lo[t] = vb4[(size_t)hl*128 + (c+1)*8 + w4];
                hi[t] = vb4[(size_t)hl*128 + 64 + (c+1)*8 + w4];
            }
        }
#pragma unroll
        for (int kt = 0; kt < 2; kt++){
            int i0 = kt*16 + 2*q, i1 = i0 + 8;
            // ---- even parity: a operand ----
            {
                float2 f0 = *(const float2*)&Asm[pr0*64 + (i0 ^ sw0)];
                float2 f1 = *(const float2*)&Asm[pr1*64 + (i0 ^ sw1)];
                float2 f2 = *(const float2*)&Asm[pr0*64 + (i1 ^ sw0)];
                float2 f3 = *(const float2*)&Asm[pr1*64 + (i1 ^ sw1)];
                uint32_t ah0 = pack_bf16(f0.x, f0.y), al0 = lo_residual(ah0, f0.x, f0.y);
                uint32_t ah1 = pack_bf16(f1.x, f1.y), al1 = lo_residual(ah1, f1.x, f1.y);
                uint32_t ah2 = pack_bf16(f2.x, f2.y), al2 = lo_residual(ah2, f2.x, f2.y);
                uint32_t ah3 = pack_bf16(f3.x, f3.y), al3 = lo_residual(ah3, f3.x, f3.y);
                int bb = ((c*2 + kt)*2 + 0)*512 + lane*2;
#pragma unroll
                for (int nt = 0; nt < 8; nt++){
                    uint2 bh = *(const uint2*)&TFWH[bb + nt*64];
                    uint2 bl = *(const uint2*)&TFWL[bb + nt*64];
                    mma16816(accE[nt], ah0, ah1, ah2, ah3, bh.x, bh.y);
                    mma16816(accE[nt], ah0, ah1, ah2, ah3, bl.x, bl.y);
                    mma16816(accE[nt], al0, al1, al2, al3, bh.x, bh.y);
                }
            }
            // ---- odd parity: b operand ----
            {
                float2 f0 = *(const float2*)&Asm[pr0*64 + ((32+i0) ^ sw0)];
                float2 f1 = *(const float2*)&Asm[pr1*64 + ((32+i0) ^ sw1)];
                float2 f2 = *(const float2*)&Asm[pr0*64 + ((32+i1) ^ sw0)];
                float2 f3 = *(const float2*)&Asm[pr1*64 + ((32+i1) ^ sw1)];
                uint32_t ah0 = pack_bf16(f0.x, f0.y), al0 = lo_residual(ah0, f0.x, f0.y);
                uint32_t ah1 = pack_bf16(f1.x, f1.y), al1 = lo_residual(ah1, f1.x, f1.y);
                uint32_t ah2 = pack_bf16(f2.x, f2.y), al2 = lo_residual(ah2, f2.x, f2.y);
                uint32_t ah3 = pack_bf16(f3.x, f3.y), al3 = lo_residual(ah3, f3.x, f3.y);
                int bb = ((c*2 + kt)*2 + 1)*512 + lane*2;
#pragma unroll
                for (int nt = 0; nt < 8; nt++){
                    uint2 bh = *(const uint2*)&TFWH[bb + nt*64];
                    uint2 bl = *(const uint2*)&TFWL[bb + nt*64];
                    mma16816(accO[nt], ah0, ah1, ah2, ah3, bh.x, bh.y);
                    mma16816(accO[nt], ah0, ah1, ah2, ah3, bl.x, bl.y);
                    mma16816(accO[nt], al0, al1, al2, al3, bh.x, bh.y);
                }
            }
        }
    }
#pragma unroll
    for (int nt = 0; nt < 8; nt++){
        int posc = nt*4 + q;
        size_t b0 = (size_t)(h0 + pr0)*4096 + ch*64;
        size_t b1 = (size_t)(h0 + pr1)*4096 + ch*64;
        d_P[b0 + 2*posc]     = make_float2(accE[nt][0], accE[nt][1]);
        d_P[b1 + 2*posc]     = make_float2(accE[nt][2], accE[nt][3]);
        d_P[b0 + 2*posc + 1] = make_float2(accO[nt][0], accO[nt][1]);
        d_P[b1 + 2*posc + 1] = make_float2(accO[nt][2], accO[nt][3]);
    }
}

// ================ forward H-DFT via mma.sync, split-K x4 ================
__global__ void __launch_bounds__(128) k_fwdH(){
    __shared__ uint32_t BsmH[32*72], BsmL[32*72];
    int x0 = blockIdx.x*32, kp = blockIdx.y;
    int tid = threadIdx.x;
    int lane = tid & 31, wid = tid >> 5;
    int q = lane & 3, r = lane >> 2;

    float acc[8][4];
#pragma unroll
    for (int nt=0; nt<8; nt++)
#pragma unroll
        for (int e=0; e<4; e++) acc[nt][e] = 0.f;

#pragma unroll
    for (int c = 0; c < 4; c++){
        __syncthreads();
        int hbase = kp*128 + c*32;
#pragma unroll
        for (int k = 0; k < 8; k++){
            int idx = tid + k*128;
            int xl = idx & 31, hh = idx >> 5;
            float2 p = d_P[(size_t)(hbase+hh)*4096 + x0 + xl];
            uint32_t hre = pack_bf16(p.x,  p.y);
            uint32_t lre = lo_residual(hre, p.x,  p.y);
            uint32_t him = pack_bf16(p.y, -p.x);
            uint32_t lim = lo_residual(him, p.y, -p.x);
            *(uint2*)&BsmH[hh*72 + 2*xl] = make_uint2(hre, him);
            *(uint2*)&BsmL[hh*72 + 2*xl] = make_uint2(lre, lim);
        }
        __syncthreads();
#pragma unroll
        for (int kt = 0; kt < 4; kt++){
            int ks = kp*16 + c*4 + kt;
            uint4 ah = *(const uint4*)&TFHAH[((wid*64 + ks)*32 + lane)*4];
            uint4 al = *(const uint4*)&TFHAL[((wid*64 + ks)*32 + lane)*4];
#pragma unroll
            for (int nt = 0; nt < 8; nt++){
                int n = nt*8 + r;
                uint32_t b0h = BsmH[(kt*8+q  )*72 + n];
                uint32_t b1h = BsmH[(kt*8+q+4)*72 + n];
                uint32_t b0l = BsmL[(kt*8+q  )*72 + n];
                uint32_t b1l = BsmL[(kt*8+q+4)*72 + n];
                mma16816(acc[nt], ah.x, ah.y, ah.z, ah.w, b0h, b1h);
                mma16816(acc[nt], ah.x, ah.y, ah.z, ah.w, b0l, b1l);
                mma16816(acc[nt], al.x, al.y, al.z, al.w, b0h, b1h);
            }
        }
    }
    int m0 = wid*16 + r;
    float2* cp = d_cp + (size_t)kp*(Md*Cc*Md);
#pragma unroll
    for (int nt = 0; nt < 8; nt++){
        int x = x0 + nt*4 + q;
        cp[(size_t)m0*4096 + x]     = make_float2(acc[nt][0], acc[nt][1]);
        cp[(size_t)(m0+8)*4096 + x] = make_float2(acc[nt][2], acc[nt][3]);
    }
}

// ---------------- reduce split-K partials ----------------
__global__ void k_cred(){
    int p = blockIdx.x*256 + threadIdx.x;
    const int S = Md*Cc*Md;
    float2 a = d_cp[p], b = d_cp[S+p], c = d_cp[2*S+p], d = d_cp[3*S+p];
    d_c[p] = make_float2(a.x+b.x+c.x+d.x, a.y+b.y+c.y+d.y);
}

// ---------------- per-mode channel mixing ----------------
__global__ void k_mix(const float* __restrict__ Ar, const float* __restrict__ Ai){
    int o  = blockIdx.y;
    int t2 = blockIdx.x*256 + threadIdx.x;
    int mode = t2*2;
    int m = mode >> 6, n = mode & 63;
    const float2* arp = (const float2*)(Ar + (size_t)o*Cc*4096 + mode);
    const float2* aip = (const float2*)(Ai + (size_t)o*Cc*4096 + mode);
    const float4* cp  = (const float4*)(d_c + ((size_t)m << 12) + n);
    float dr0=0.f, di0=0.f, dr1=0.f, di1=0.f;
#pragma unroll 8
    for (int i=0; i<Cc; i++){
        float2 a = __ldg(arp + (size_t)i*2048);
        float2 b = __ldg(aip + (size_t)i*2048);
        float4 cc = cp[i*32];
        dr0 += a.x*cc.x - b.x*cc.y;  di0 += a.x*cc.y + b.x*cc.x;
        dr1 += a.y*cc.z - b.y*cc.w;  di1 += a.y*cc.w + b.y*cc.z;
    }
    *(float4*)(d_dm + ((size_t)m << 12) + (o << 6) + n) = make_float4(dr0, di0, dr1, di1);
}

// ================ inverse H-DFT via mma.sync ================
__global__ void __launch_bounds__(128) k_invH(){
    __shared__ uint32_t BsmH[64*72], BsmL[64*72];
    int x0 = blockIdx.x*32, h0 = blockIdx.y*64;
    int tid = threadIdx.x;
    int lane = tid & 31, wid = tid >> 5;
    int q = lane & 3, r = lane >> 2;

#pragma unroll
    for (int k = 0; k < 16; k++){
        int idx = tid + k*128;
        int xl = idx & 31, m = idx >> 5;
        float2 p = d_dm[(size_t)m*4096 + x0 + xl];
        uint32_t hre = pack_bf16(p.x, -p.y);
        uint32_t lre = lo_residual(hre, p.x, -p.y);
        uint32_t him = pack_bf16(p.y,  p.x);
        uint32_t lim = lo_residual(him, p.y,  p.x);
        *(uint2*)&BsmH[m*72 + 2*xl] = make_uint2(hre, him);
        *(uint2*)&BsmL[m*72 + 2*xl] = make_uint2(lre, lim);
    }
    __syncthreads();

    float acc[8][4];
#pragma unroll
    for (int nt=0; nt<8; nt++)
#pragma unroll
        for (int e=0; e<4; e++) acc[nt][e] = 0.f;

    int rg = blockIdx.y*4 + wid;
#pragma unroll
    for (int ks = 0; ks < 8; ks++){
        uint4 ah = *(const uint4*)&TIHAH[((rg*8 + ks)*32 + lane)*4];
        uint4 al = *(const uint4*)&TIHAL[((rg*8 + ks)*32 + lane)*4];
#pragma unroll
        for (int nt = 0; nt < 8; nt++){
            int n = nt*8 + r;
            uint32_t b0h = BsmH[(ks*8+q  )*72 + n];
            uint32_t b1h = BsmH[(ks*8+q+4)*72 + n];
            uint32_t b0l = BsmL[(ks*8+q  )*72 + n];
            uint32_t b1l = BsmL[(ks*8+q+4)*72 + n];
            mma16816(acc[nt], ah.x, ah.y, ah.z, ah.w, b0h, b1h);
            mma16816(acc[nt], ah.x, ah.y, ah.z, ah.w, b0l, b1l);
            mma16816(acc[nt], al.x, al.y, al.z, al.w, b0h, b1h);
        }
    }
    int hrow = h0 + wid*16 + r;
#pragma unroll
    for (int nt = 0; nt < 8; nt++){
        int x = x0 + nt*4 + q;
        d_G[(size_t)hrow*4096 + x]     = make_float2(acc[nt][0], acc[nt][1]);
        d_G[(size_t)(hrow+8)*4096 + x] = make_float2(acc[nt][2], acc[nt][3]);
    }
}

// ================ inverse W-DFT via mma.sync (R10 version) ================
__global__ void __launch_bounds__(128) k_invW(){
    __shared__ float Asm[64*128];
    int ch = blockIdx.y;
    int h0 = (blockIdx.x >> 2)*64;
    int wt = blockIdx.x & 3;
    int tid = threadIdx.x;
    int lane = tid & 31, wid = tid >> 5;
    int q = lane & 3, r = lane >> 2;
    const float* Gf = (const float*)d_G;

    int pr0 = wid*16 + r, pr1 = pr0 + 8;
    int sw0 = (pr0 & 7) << 3, sw1 = (pr1 & 7) << 3;

#pragma unroll
    for (int t = 0; t < 64; t++){
        int idx = tid + t*128;
        int hl = idx >> 7, cl = idx & 127;
        Asm[hl*128 + (cl ^ ((hl & 7) << 3))] =
            Gf[(size_t)(h0+hl)*8192 + ch*128 + cl];
    }
    __syncthreads();

    float acc[16][4];
#pragma unroll
    for (int nt=0; nt<16; nt++)
#pragma unroll
        for (int e=0; e<4; e++) acc[nt][e] = 0.f;

#pragma unroll
    for (int kt = 0; kt < 8; kt++){
        int i0 = kt*16 + 2*q, i1 = i0 + 8;
        float2 f0 = *(const float2*)&Asm[pr0*128 + (i0 ^ sw0)];
        float2 f1 = *(const float2*)&Asm[pr1*128 + (i0 ^ sw1)];
        float2 f2 = *(const float2*)&Asm[pr0*128 + (i1 ^ sw0)];
        float2 f3 = *(const float2*)&Asm[pr1*128 + (i1 ^ sw1)];
        uint32_t ah0 = pack_bf16(f0.x, f0.y), al0 = lo_residual(ah0, f0.x, f0.y);
        uint32_t ah1 = pack_bf16(f1.x, f1.y), al1 = lo_residual(ah1, f1.x, f1.y);
        uint32_t ah2 = pack_bf16(f2.x, f2.y), al2 = lo_residual(ah2, f2.x, f2.y);
        uint32_t ah3 = pack_bf16(f3.x, f3.y), al3 = lo_residual(ah3, f3.x, f3.y);
        int bbase = (wt*8 + kt)*1024 + lane*2;
#pragma unroll
        for (int nt = 0; nt < 16; nt++){
            uint2 bh = *(const uint2*)&TIWH[bbase + nt*64];
            uint2 bl = *(const uint2*)&TIWL[bbase + nt*64];
            mma16816(acc[nt], ah0, ah1, ah2, ah3, bh.x, bh.y);
            mma16816(acc[nt], ah0, ah1, ah2, ah3, bl.x, bl.y);
            mma16816(acc[nt], al0, al1, al2, al3, bh.x, bh.y);
        }
    }
#pragma unroll
    for (int nt = 0; nt < 16; nt++){
        int w = wt*128 + nt*8 + 2*q;
        *(float2*)&d_s[((size_t)ch*Hd + h0 + pr0)*Wd + w] = make_float2(acc[nt][0], acc[nt][1]);
        *(float2*)&d_s[((size_t)ch*Hd + h0 + pr1)*Wd + w] = make_float2(acc[nt][2], acc[nt][3]);
    }
}

// ================= mma.sync bf16 fused residual block v2 =================
#define RT2 2
__global__ void __launch_bounds__(256) k_resid_mma(
        int l,
        const float* __restrict__ b1, const float* __restrict__ b2,
        const float* __restrict__ dw, const float* __restrict__ db,
        float* __restrict__ dout){
    __shared__ float Asm[128*64];

    int tid  = threadIdx.x;
    int lane = tid & 31, wid = tid >> 5;
    int q = lane & 3, r = lane >> 2;

    const uint2* w1h = WBF + ((l*2 + 0)*2 + 0)*1024;
    const uint2* w1l = WBF + ((l*2 + 0)*2 + 1)*1024;
    const uint2* w2h = WBF + ((l*2 + 1)*2 + 0)*1024;
    const uint2* w2l = WBF + ((l*2 + 1)*2 + 1)*1024;

    int wpx = wid * 16;
    int pr0 = wpx + r, pr1 = pr0 + 8;
    int sw0 = (pr0 & 7) << 3, sw1 = (pr1 & 7) << 3;
    float db0 = (dout != nullptr) ? __ldg(db) : 0.f;

    for (int t = 0; t < RT2; t++){
        size_t pbase = ((size_t)blockIdx.x*RT2 + t)*128;
        __syncthreads();
#pragma unroll 8
        for (int c = 0; c < 32; c++){
            int idx = tid + c*256;
            int i = idx >> 7, px = idx & 127;
            Asm[px*64 + (i ^ ((px & 7) << 3))] = d_s[(size_t)i*HW + pbase + px];
        }
        __syncthreads();

        float acc1[8][4];
#pragma unroll
        for (int nt=0; nt<8; nt++)
#pragma unroll
            for (int e=0; e<4; e++) acc1[nt][e] = 0.f;

#pragma unroll
        for (int kt = 0; kt < 4; kt++){
            int i0 = kt*16 + 2*q, i1 = i0 + 8;
            float2 f0 = *(const float2*)&Asm[pr0*64 + (i0 ^ sw0)];
            float2 f1 = *(const float2*)&Asm[pr1*64 + (i0 ^ sw1)];
            float2 f2 = *(const float2*)&Asm[pr0*64 + (i1 ^ sw0)];
            float2 f3 = *(const float2*)&Asm[pr1*64 + (i1 ^ sw1)];
            uint32_t ah0 = pack_bf16(f0.x, f0.y), al0 = lo_residual(ah0, f0.x, f0.y);
            uint32_t ah1 = pack_bf16(f1.x, f1.y), al1 = lo_residual(ah1, f1.x, f1.y);
            uint32_t ah2 = pack_bf16(f2.x, f2.y), al2 = lo_residual(ah2, f2.x, f2.y);
            uint32_t ah3 = pack_bf16(f3.x, f3.y), al3 = lo_residual(ah3, f3.x, f3.y);
#pragma unroll
            for (int nt = 0; nt < 8; nt++){
                int fi = (nt*4 + kt)*32 + lane;
                uint2 bh = __ldg(w1h + fi);
                uint2 bl = __ldg(w1l + fi);
                mma16816(acc1[nt], ah0, ah1, ah2, ah3, bh.x, bh.y);
                mma16816(acc1[nt], ah0, ah1, ah2, ah3, bl.x, bl.y);
                mma16816(acc1[nt], al0, al1, al2, al3, bh.x, bh.y);
            }
        }

        uint32_t a2h[4][4], a2l[4][4];
#pragma unroll
        for (int nt = 0; nt < 8; nt++){
            int j0 = nt*8 + 2*q;
            float bj0 = __ldg(b1 + j0), bj1 = __ldg(b1 + j0 + 1);
            float g0 = gelu_f(acc1[nt][0] + bj0);
            float g1 = gelu_f(acc1[nt][1] + bj1);
            float g2 = gelu_f(acc1[nt][2] + bj0);
            float g3 = gelu_f(acc1[nt][3] + bj1);
            uint32_t h01 = pack_bf16(g0, g1), l01 = lo_residual(h01, g0, g1);
            uint32_t h23 = pack_bf16(g2, g3), l23 = lo_residual(h23, g2, g3);
            int kt = nt >> 1;
            if ((nt & 1) == 0){
                a2h[kt][0] = h01; a2h[kt][1] = h23;
                a2l[kt][0] = l01; a2l[kt][1] = l23;
            } else {
                a2h[kt][2] = h01; a2h[kt][3] = h23;
                a2l[kt][2] = l01; a2l[kt][3] = l23;
            }
        }

        float acc2[8][4];
#pragma unroll
        for (int nt=0; nt<8; nt++)
#pragma unroll
            for (int e=0; e<4; e++) acc2[nt][e] = 0.f;
#pragma unroll
        for (int kt = 0; kt < 4; kt++){
#pragma unroll
            for (int nt = 0; nt < 8; nt++){
                int fi = (nt*4 + kt)*32 + lane;
                uint2 bh = __ldg(w2h + fi);
                uint2 bl = __ldg(w2l + fi);
                mma16816(acc2[nt], a2h[kt][0], a2h[kt][1], a2h[kt][2], a2h[kt][3], bh.x, bh.y);
                mma16816(acc2[nt], a2h[kt][0], a2h[kt][1], a2h[kt][2], a2h[kt][3], bl.x, bl.y);
                mma16816(acc2[nt], a2l[kt][0], a2l[kt][1], a2l[kt][2], a2l[kt][3], bh.x, bh.y);
            }
        }

        size_t p0 = pbase + wpx + r, p1 = p0 + 8;
        float sum0 = 0.f, sum1 = 0.f;
#pragma unroll
        for (int nt = 0; nt < 8; nt++){
            int ch0 = nt*8 + 2*q, ch1 = ch0 + 1;
            float bb0 = __ldg(b2 + ch0), bb1 = __ldg(b2 + ch1);
            float v00 = d_v[(size_t)ch0*HW + p0] + gelu_f(acc2[nt][0] + bb0);
            float v10 = d_v[(size_t)ch1*HW + p0] + gelu_f(acc2[nt][1] + bb1);
            float v01 = d_v[(size_t)ch0*HW + p1] + gelu_f(acc2[nt][2] + bb0);
            float v11 = d_v[(size_t)ch1*HW + p1] + gelu_f(acc2[nt][3] + bb1);
            if (dout == nullptr){
                d_v[(size_t)ch0*HW + p0] = v00;
                d_v[(size_t)ch1*HW + p0] = v10;
                d_v[(size_t)ch0*HW + p1] = v01;
                d_v[(size_t)ch1*HW + p1] = v11;
            } else {
                float w0 = __ldg(dw + ch0), w1 = __ldg(dw + ch1);
                sum0 += w0*v00 + w1*v10;
                sum1 += w0*v01 + w1*v11;
            }
        }
        if (dout != nullptr){
            sum0 += __shfl_xor_sync(0xffffffffu, sum0, 1);
            sum0 += __shfl_xor_sync(0xffffffffu, sum0, 2);
            sum1 += __shfl_xor_sync(0xffffffffu, sum1, 1);
            sum1 += __shfl_xor_sync(0xffffffffu, sum1, 2);
            if (q == 0){
                dout[p0] = sum0 + db0;
                dout[p1] = sum1 + db0;
            }
        }
    }
}

// ---------------- launch ----------------
extern "C" void kernel_launch(void* const* d_in, const int* in_sizes, int n_in,
                              void* d_out, int out_size){
    const float* u    = (const float*)d_in[0];
    const float* x    = (const float*)d_in[1];
    const float* encw = (const float*)d_in[2];
    const float* encb = (const float*)d_in[3];
    const float* decw = (const float*)d_in[4];
    const float* decb = (const float*)d_in[5];
    const float* c1w  = (const float*)d_in[6];
    const float* c1b  = (const float*)d_in[7];
    const float* c2w  = (const float*)d_in[8];
    const float* c2b  = (const float*)d_in[9];
    const float* Are  = (const float*)d_in[10];
    const float* Aim  = (const float*)d_in[11];
    float* out = (float*)d_out;

    k_tables<<<128, 256>>>();
    k_wprep<<<32, 256>>>(c1w, c2w);
    k_enc<<<dim3(HW/256, Cc), 256>>>(u, x, encw, encb);

    for (int l=0; l<Ll; l++){
        k_fwdW<<<dim3(8, Cc), 128>>>();
        k_fwdH<<<dim3(128, 4), 128>>>();
        k_cred<<<1024, 256>>>();
        k_mix<<<dim3(8, Cc), 256>>>(Are + (size_t)l*Cc*Cc*4096,
                                    Aim + (size_t)l*Cc*Cc*4096);
        k_invH<<<dim3(128, 8), 128>>>();
        k_invW<<<dim3(32, Cc), 128>>>();
        bool last = (l == Ll-1);
        k_resid_mma<<<HW/(128*RT2), 256>>>(l, c1b + l*64, c2b + l*64,
                                           last ? decw : nullptr,
                                           last ? decb : nullptr,
                                           last ? out  : nullptr);
    }
}

// round 15
// speedup vs baseline: 1.4200x; 1.1278x over previous
#include <cuda_runtime.h>
#include <cuda_bf16.h>
#include <cstdint>

#define Hd 512
#define Wd 512
#define HW (512*512)
#define Cc 64
#define Md 64
#define Ll 4

// ---------------- scratch (device globals) ----------------
__device__ float  d_v[Cc*HW];
__device__ float  d_s[Cc*HW];
__device__ float2 d_P[Hd*Cc*Md];       // [h][ch*64+n]
__device__ float2 d_G[Hd*Cc*Md];       // [h][ch*64+n]
__device__ float2 d_c[Md*Cc*Md];
__device__ float2 d_cp[4*Md*Cc*Md];
__device__ float2 d_dm[Md*Cc*Md];
// fwdW folded B-frag table: idx=(((c*2+kt)*2+p)*8+nt)*32+lane, elems idx*2+rr
__device__ uint32_t TFWH[32768], TFWL[32768];
// invW folded B-frag table: idx=(((wq*4+kt)*2+p)*8+nt)*32+lane, elems idx*2+rr
__device__ uint32_t TIWH[32768], TIWL[32768];
__device__ uint32_t TFHAH[32768], TFHAL[32768];
__device__ uint32_t TIHAH[32768], TIHAL[32768];
__device__ uint2 WBF[4*2*2*1024];

__device__ __forceinline__ float gelu_f(float x){
    float y = 0.7978845608028654f*(x + 0.044715f*x*x*x);
    float e = __expf(2.0f*y);
    float t = 1.0f - __fdividef(2.0f, e + 1.0f);
    return 0.5f*x*(1.0f + t);
}

__device__ __forceinline__ uint32_t pack_bf16(float lo, float hi){
    uint32_t r;
    asm("cvt.rn.bf16x2.f32 %0, %1, %2;" : "=r"(r) : "f"(hi), "f"(lo));
    return r;
}
__device__ __forceinline__ uint32_t lo_residual(uint32_t hp, float f0, float f1){
    float l0 = f0 - __uint_as_float(hp << 16);
    float l1 = f1 - __uint_as_float(hp & 0xFFFF0000u);
    return pack_bf16(l0, l1);
}
__device__ __forceinline__ void mma16816(float* d,
        uint32_t a0, uint32_t a1, uint32_t a2, uint32_t a3,
        uint32_t b0, uint32_t b1){
    asm volatile(
        "mma.sync.aligned.m16n8k16.row.col.f32.bf16.bf16.f32 "
        "{%0,%1,%2,%3}, {%4,%5,%6,%7}, {%8,%9}, {%0,%1,%2,%3};"
        : "+f"(d[0]), "+f"(d[1]), "+f"(d[2]), "+f"(d[3])
        : "r"(a0), "r"(a1), "r"(a2), "r"(a3), "r"(b0), "r"(b1));
}

// ---------------- tables ----------------
__global__ void k_tables(){
    int idx = blockIdx.x*256 + threadIdx.x;
    // folded fwdW B frags (even/odd parity over K=256)
    if (idx < 8192){
        int lane = idx & 31;
        int nt = (idx >> 5) & 7;
        int p  = (idx >> 8) & 1;
        int kt = (idx >> 9) & 1;
        int c  = (idx >> 10) & 7;
        int col = nt*8 + (lane >> 2);
        int posc = col >> 1, ri = col & 1;
        int n = 2*posc + p;
        const float nrm = 1.0f/(float)(HW);
#pragma unroll
        for (int rr = 0; rr < 2; rr++){
            int wk = c*32 + kt*16 + (lane & 3)*2 + rr*8;
            float s0, c0, s1, c1;
            sincospif((float)(n*wk)     * (1.0f/256.0f), &s0, &c0);
            sincospif((float)(n*(wk+1)) * (1.0f/256.0f), &s1, &c1);
            float f0 = (ri==0) ? c0*nrm : -s0*nrm;
            float f1 = (ri==0) ? c1*nrm : -s1*nrm;
            uint32_t hp = pack_bf16(f0, f1);
            TFWH[idx*2+rr] = hp;
            TFWL[idx*2+rr] = lo_residual(hp, f0, f1);
        }
    }
    // folded invW B frags (even/odd parity over modes, K=64 per parity)
    if (idx < 8192){
        int lane = idx & 31;
        int nt = (idx >> 5) & 7;
        int p  = (idx >> 8) & 1;
        int kt = (idx >> 9) & 3;
        int wq = idx >> 11;                 // 0..3
        int w = wq*64 + nt*8 + (lane >> 2);
#pragma unroll
        for (int rr = 0; rr < 2; rr++){
            int k0 = kt*16 + (lane & 3)*2 + rr*8;   // even -> (re,im) pair of n'
            int n = 2*(k0 >> 1) + p;
            float a = (n==0) ? 1.0f : 2.0f;
            float s, c;
            sincospif((float)(n*w) * (1.0f/256.0f), &s, &c);
            float f0 =  a*c;
            float f1 = -a*s;
            uint32_t hp = pack_bf16(f0, f1);
            TIWH[idx*2+rr] = hp;
            TIWL[idx*2+rr] = lo_residual(hp, f0, f1);
        }
    }
    {
        int reg = idx & 3, lane = (idx >> 2) & 31, ks = (idx >> 7) & 63, rg = (idx >> 13) & 3;
        int r = lane >> 2, q = lane & 3;
        int m  = rg*16 + r + (reg & 1)*8;
        int kb = ks*16 + 2*q + (reg >> 1)*8;
        int h  = kb >> 1;
        float s, c;
        sincospif((float)((m-32)*h) * (1.0f/256.0f), &s, &c);
        uint32_t hp = pack_bf16(c, s);
        TFHAH[idx] = hp;
        TFHAL[idx] = lo_residual(hp, c, s);
    }
    {
        int reg = idx & 3, lane = (idx >> 2) & 31, ks = (idx >> 7) & 7, rg = idx >> 10;
        int r = lane >> 2, q = lane & 3;
        int h  = rg*16 + r + (reg & 1)*8;
        int kb = ks*16 + 2*q + (reg >> 1)*8;
        int m  = kb >> 1;
        float s, c;
        sincospif((float)((m-32)*h) * (1.0f/256.0f), &s, &c);
        uint32_t hp = pack_bf16(c, s);
        TIHAH[idx] = hp;
        TIHAL[idx] = lo_residual(hp, c, s);
    }
}

// ---------------- residual-weight fragment tables ----------------
__global__ void k_wprep(const float* __restrict__ c1w, const float* __restrict__ c2w){
    int idx = blockIdx.x*256 + threadIdx.x;
    int lane = idx & 31;
    int kt   = (idx >> 5) & 3;
    int nt   = (idx >> 7) & 7;
    int mat  = (idx >> 10) & 1;
    int l    = idx >> 11;
    int r = lane >> 2, q = lane & 3;
    const float* W = (mat ? c2w : c1w) + l*4096;
    int n  = nt*8 + r;
    int k0 = kt*16 + 2*q;
    int k2 = k0 + 8;
    float f0 = W[n*64 + k0], f1 = W[n*64 + k0 + 1];
    float f2 = W[n*64 + k2], f3 = W[n*64 + k2 + 1];
    uint32_t h0 = pack_bf16(f0, f1), h1 = pack_bf16(f2, f3);
    uint32_t l0 = lo_residual(h0, f0, f1), l1 = lo_residual(h1, f2, f3);
    int fi = (nt*4 + kt)*32 + lane;
    WBF[((l*2 + mat)*2 + 0)*1024 + fi] = make_uint2(h0, h1);
    WBF[((l*2 + mat)*2 + 1)*1024 + fi] = make_uint2(l0, l1);
}

// ---------------- encoder ----------------
__global__ void k_enc(const float* __restrict__ u, const float* __restrict__ x,
                      const float* __restrict__ ew, const float* __restrict__ eb){
    int p  = blockIdx.x*256 + threadIdx.x;
    int ch = blockIdx.y;
    float w0 = ew[ch*3+0], w1 = ew[ch*3+1], w2 = ew[ch*3+2];
    d_v[(size_t)ch*HW + p] = w0*x[p] + w1*x[HW+p] + w2*u[p] + eb[ch];
}

// ================ forward W-DFT via mma.sync (even/odd folded, K=256) ================
__global__ void __launch_bounds__(128) k_fwdW(){
    __shared__ float Asm[64*64];
    int ch = blockIdx.y, h0 = blockIdx.x*64;
    int tid = threadIdx.x;
    int lane = tid & 31, wid = tid >> 5;
    int q = lane & 3, r = lane >> 2;
    const float4* vb4 = (const float4*)(d_v + ((size_t)ch*Hd + h0)*Wd);

    int pr0 = wid*16 + r, pr1 = pr0 + 8;
    int sw0 = (pr0 & 7) << 3, sw1 = (pr1 & 7) << 3;

    float accE[8][4], accO[8][4];
#pragma unroll
    for (int nt=0; nt<8; nt++)
#pragma unroll
        for (int e=0; e<4; e++){ accE[nt][e] = 0.f; accO[nt][e] = 0.f; }

    float4 lo[4], hi[4];
#pragma unroll
    for (int t=0;t<4;t++){
        int slot = tid + t*128;
        int hl = slot >> 3, w4 = slot & 7;
        lo[t] = vb4[(size_t)hl*128 + w4];
        hi[t] = vb4[(size_t)hl*128 + 64 + w4];
    }

    for (int c = 0; c < 8; c++){
        __syncthreads();
#pragma unroll
        for (int t=0;t<4;t++){
            int slot = tid + t*128;
            int hl = slot >> 3, w4 = slot & 7;
            float4 av, bv;
            av.x = lo[t].x + hi[t].x;  bv.x = lo[t].x - hi[t].x;
            av.y = lo[t].y + hi[t].y;  bv.y = lo[t].y - hi[t].y;
            av.z = lo[t].z + hi[t].z;  bv.z = lo[t].z - hi[t].z;
            av.w = lo[t].w + hi[t].w;  bv.w = lo[t].w - hi[t].w;
            int sw = (hl & 7) << 3;
            *(float4*)&Asm[hl*64 + ((w4*4) ^ sw)]      = av;
            *(float4*)&Asm[hl*64 + ((32 + w4*4) ^ sw)] = bv;
        }
        __syncthreads();
        if (c < 7){
#pragma unroll
            for (int t=0;t<4;t++){
                int slot = tid + t*128;
                int hl = slot >> 3, w4 = slot & 7;
                lo[t] = vb4[(size_t)hl*128 + (c+1)*8 + w4];
                hi[t] = vb4[(size_t)hl*128 + 64 + (c+1)*8 + w4];
            }
        }
#pragma unroll
        for (int kt = 0; kt < 2; kt++){
            int i0 = kt*16 + 2*q, i1 = i0 + 8;
            {
                float2 f0 = *(const float2*)&Asm[pr0*64 + (i0 ^ sw0)];
                float2 f1 = *(const float2*)&Asm[pr1*64 + (i0 ^ sw1)];
                float2 f2 = *(const float2*)&Asm[pr0*64 + (i1 ^ sw0)];
                float2 f3 = *(const float2*)&Asm[pr1*64 + (i1 ^ sw1)];
                uint32_t ah0 = pack_bf16(f0.x, f0.y), al0 = lo_residual(ah0, f0.x, f0.y);
                uint32_t ah1 = pack_bf16(f1.x, f1.y), al1 = lo_residual(ah1, f1.x, f1.y);
                uint32_t ah2 = pack_bf16(f2.x, f2.y), al2 = lo_residual(ah2, f2.x, f2.y);
                uint32_t ah3 = pack_bf16(f3.x, f3.y), al3 = lo_residual(ah3, f3.x, f3.y);
                int bb = ((c*2 + kt)*2 + 0)*512 + lane*2;
#pragma unroll
                for (int nt = 0; nt < 8; nt++){
                    uint2 bh = *(const uint2*)&TFWH[bb + nt*64];
                    uint2 bl = *(const uint2*)&TFWL[bb + nt*64];
                    mma16816(accE[nt], ah0, ah1, ah2, ah3, bh.x, bh.y);
                    mma16816(accE[nt], ah0, ah1, ah2, ah3, bl.x, bl.y);
                    mma16816(accE[nt], al0, al1, al2, al3, bh.x, bh.y);
                }
            }
            {
                float2 f0 = *(const float2*)&Asm[pr0*64 + ((32+i0) ^ sw0)];
                float2 f1 = *(const float2*)&Asm[pr1*64 + ((32+i0) ^ sw1)];
                float2 f2 = *(const float2*)&Asm[pr0*64 + ((32+i1) ^ sw0)];
                float2 f3 = *(const float2*)&Asm[pr1*64 + ((32+i1) ^ sw1)];
                uint32_t ah0 = pack_bf16(f0.x, f0.y), al0 = lo_residual(ah0, f0.x, f0.y);
                uint32_t ah1 = pack_bf16(f1.x, f1.y), al1 = lo_residual(ah1, f1.x, f1.y);
                uint32_t ah2 = pack_bf16(f2.x, f2.y), al2 = lo_residual(ah2, f2.x, f2.y);
                uint32_t ah3 = pack_bf16(f3.x, f3.y), al3 = lo_residual(ah3, f3.x, f3.y);
                int bb = ((c*2 + kt)*2 + 1)*512 + lane*2;
#pragma unroll
                for (int nt = 0; nt < 8; nt++){
                    uint2 bh = *(const uint2*)&TFWH[bb + nt*64];
                    uint2 bl = *(const uint2*)&TFWL[bb + nt*64];
                    mma16816(accO[nt], ah0, ah1, ah2, ah3, bh.x, bh.y);
                    mma16816(accO[nt], ah0, ah1, ah2, ah3, bl.x, bl.y);
                    mma16816(accO[nt], al0, al1, al2, al3, bh.x, bh.y);
                }
            }
        }
    }
#pragma unroll
    for (int nt = 0; nt < 8; nt++){
        int posc = nt*4 + q;
        size_t b0 = (size_t)(h0 + pr0)*4096 + ch*64;
        size_t b1 = (size_t)(h0 + pr1)*4096 + ch*64;
        d_P[b0 + 2*posc]     = make_float2(accE[nt][0], accE[nt][1]);
        d_P[b1 + 2*posc]     = make_float2(accE[nt][2], accE[nt][3]);
        d_P[b0 + 2*posc + 1] = make_float2(accO[nt][0], accO[nt][1]);
        d_P[b1 + 2*posc + 1] = make_float2(accO[nt][2], accO[nt][3]);
    }
}

// ================ forward H-DFT via mma.sync, split-K x4 ================
__global__ void __launch_bounds__(128) k_fwdH(){
    __shared__ uint32_t BsmH[32*72], BsmL[32*72];
    int x0 = blockIdx.x*32, kp = blockIdx.y;
    int tid = threadIdx.x;
    int lane = tid & 31, wid = tid >> 5;
    int q = lane & 3, r = lane >> 2;

    float acc[8][4];
#pragma unroll
    for (int nt=0; nt<8; nt++)
#pragma unroll
        for (int e=0; e<4; e++) acc[nt][e] = 0.f;

#pragma unroll
    for (int c = 0; c < 4; c++){
        __syncthreads();
        int hbase = kp*128 + c*32;
#pragma unroll
        for (int k = 0; k < 8; k++){
            int idx = tid + k*128;
            int xl = idx & 31, hh = idx >> 5;
            float2 p = d_P[(size_t)(hbase+hh)*4096 + x0 + xl];
            uint32_t hre = pack_bf16(p.x,  p.y);
            uint32_t lre = lo_residual(hre, p.x,  p.y);
            uint32_t him = pack_bf16(p.y, -p.x);
            uint32_t lim = lo_residual(him, p.y, -p.x);
            *(uint2*)&BsmH[hh*72 + 2*xl] = make_uint2(hre, him);
            *(uint2*)&BsmL[hh*72 + 2*xl] = make_uint2(lre, lim);
        }
        __syncthreads();
#pragma unroll
        for (int kt = 0; kt < 4; kt++){
            int ks = kp*16 + c*4 + kt;
            uint4 ah = *(const uint4*)&TFHAH[((wid*64 + ks)*32 + lane)*4];
            uint4 al = *(const uint4*)&TFHAL[((wid*64 + ks)*32 + lane)*4];
#pragma unroll
            for (int nt = 0; nt < 8; nt++){
                int n = nt*8 + r;
                uint32_t b0h = BsmH[(kt*8+q  )*72 + n];
                uint32_t b1h = BsmH[(kt*8+q+4)*72 + n];
                uint32_t b0l = BsmL[(kt*8+q  )*72 + n];
                uint32_t b1l = BsmL[(kt*8+q+4)*72 + n];
                mma16816(acc[nt], ah.x, ah.y, ah.z, ah.w, b0h, b1h);
                mma16816(acc[nt], ah.x, ah.y, ah.z, ah.w, b0l, b1l);
                mma16816(acc[nt], al.x, al.y, al.z, al.w, b0h, b1h);
            }
        }
    }
    int m0 = wid*16 + r;
    float2* cp = d_cp + (size_t)kp*(Md*Cc*Md);
#pragma unroll
    for (int nt = 0; nt < 8; nt++){
        int x = x0 + nt*4 + q;
        cp[(size_t)m0*4096 + x]     = make_float2(acc[nt][0], acc[nt][1]);
        cp[(size_t)(m0+8)*4096 + x] = make_float2(acc[nt][2], acc[nt][3]);
    }
}

// ---------------- reduce split-K partials ----------------
__global__ void k_cred(){
    int p = blockIdx.x*256 + threadIdx.x;
    const int S = Md*Cc*Md;
    float2 a = d_cp[p], b = d_cp[S+p], c = d_cp[2*S+p], d = d_cp[3*S+p];
    d_c[p] = make_float2(a.x+b.x+c.x+d.x, a.y+b.y+c.y+d.y);
}

// ---------------- per-mode channel mixing ----------------
__global__ void k_mix(const float* __restrict__ Ar, const float* __restrict__ Ai){
    int o  = blockIdx.y;
    int t2 = blockIdx.x*256 + threadIdx.x;
    int mode = t2*2;
    int m = mode >> 6, n = mode & 63;
    const float2* arp = (const float2*)(Ar + (size_t)o*Cc*4096 + mode);
    const float2* aip = (const float2*)(Ai + (size_t)o*Cc*4096 + mode);
    const float4* cp  = (const float4*)(d_c + ((size_t)m << 12) + n);
    float dr0=0.f, di0=0.f, dr1=0.f, di1=0.f;
#pragma unroll 8
    for (int i=0; i<Cc; i++){
        float2 a = __ldg(arp + (size_t)i*2048);
        float2 b = __ldg(aip + (size_t)i*2048);
        float4 cc = cp[i*32];
        dr0 += a.x*cc.x - b.x*cc.y;  di0 += a.x*cc.y + b.x*cc.x;
        dr1 += a.y*cc.z - b.y*cc.w;  di1 += a.y*cc.w + b.y*cc.z;
    }
    *(float4*)(d_dm + ((size_t)m << 12) + (o << 6) + n) = make_float4(dr0, di0, dr1, di1);
}

// ================ inverse H-DFT via mma.sync ================
__global__ void __launch_bounds__(128) k_invH(){
    __shared__ uint32_t BsmH[64*72], BsmL[64*72];
    int x0 = blockIdx.x*32, h0 = blockIdx.y*64;
    int tid = threadIdx.x;
    int lane = tid & 31, wid = tid >> 5;
    int q = lane & 3, r = lane >> 2;

#pragma unroll
    for (int k = 0; k < 16; k++){
        int idx = tid + k*128;
        int xl = idx & 31, m = idx >> 5;
        float2 p = d_dm[(size_t)m*4096 + x0 + xl];
        uint32_t hre = pack_bf16(p.x, -p.y);
        uint32_t lre = lo_residual(hre, p.x, -p.y);
        uint32_t him = pack_bf16(p.y,  p.x);
        uint32_t lim = lo_residual(him, p.y,  p.x);
        *(uint2*)&BsmH[m*72 + 2*xl] = make_uint2(hre, him);
        *(uint2*)&BsmL[m*72 + 2*xl] = make_uint2(lre, lim);
    }
    __syncthreads();

    float acc[8][4];
#pragma unroll
    for (int nt=0; nt<8; nt++)
#pragma unroll
        for (int e=0; e<4; e++) acc[nt][e] = 0.f;

    int rg = blockIdx.y*4 + wid;
#pragma unroll
    for (int ks = 0; ks < 8; ks++){
        uint4 ah = *(const uint4*)&TIHAH[((rg*8 + ks)*32 + lane)*4];
        uint4 al = *(const uint4*)&TIHAL[((rg*8 + ks)*32 + lane)*4];
#pragma unroll
        for (int nt = 0; nt < 8; nt++){
            int n = nt*8 + r;
            uint32_t b0h = BsmH[(ks*8+q  )*72 + n];
            uint32_t b1h = BsmH[(ks*8+q+4)*72 + n];
            uint32_t b0l = BsmL[(ks*8+q  )*72 + n];
            uint32_t b1l = BsmL[(ks*8+q+4)*72 + n];
            mma16816(acc[nt], ah.x, ah.y, ah.z, ah.w, b0h, b1h);
            mma16816(acc[nt], ah.x, ah.y, ah.z, ah.w, b0l, b1l);
            mma16816(acc[nt], al.x, al.y, al.z, al.w, b0h, b1h);
        }
    }
    int hrow = h0 + wid*16 + r;
#pragma unroll
    for (int nt = 0; nt < 8; nt++){
        int x = x0 + nt*4 + q;
        d_G[(size_t)hrow*4096 + x]     = make_float2(acc[nt][0], acc[nt][1]);
        d_G[(size_t)(hrow+8)*4096 + x] = make_float2(acc[nt][2], acc[nt][3]);
    }
}

// ================ inverse W-DFT via mma.sync (even/odd folded, K=64 per parity) ====
// Each block: 64 h-rows x 64 w' columns (wq quarter). A staged with parity split:
// even-n (mode,ri) pairs -> smem cols 0-63, odd-n -> 64-127.
__global__ void __launch_bounds__(128) k_invW(){
    __shared__ float Asm[64*128];
    int ch = blockIdx.y;
    int h0 = (blockIdx.x >> 2)*64;
    int wq = blockIdx.x & 3;
    int tid = threadIdx.x;
    int lane = tid & 31, wid = tid >> 5;
    int q = lane & 3, r = lane >> 2;
    const float* Gf = (const float*)d_G;

    int pr0 = wid*16 + r, pr1 = pr0 + 8;
    int sw0 = (pr0 & 7) << 3, sw1 = (pr1 & 7) << 3;

    // stage with parity reorganization
#pragma unroll
    for (int t = 0; t < 64; t++){
        int idx = tid + t*128;
        int hl = idx >> 7, cl = idx & 127;
        int n = cl >> 1, ri = cl & 1;
        int inner = ((n >> 1) << 1) | ri;
        int dcol = ((n & 1) << 6) | (inner ^ ((hl & 7) << 3));
        Asm[hl*128 + dcol] = Gf[(size_t)(h0+hl)*8192 + ch*128 + cl];
    }
    __syncthreads();

    float accE[8][4], accO[8][4];
#pragma unroll
    for (int nt=0; nt<8; nt++)
#pragma unroll
        for (int e=0; e<4; e++){ accE[nt][e] = 0.f; accO[nt][e] = 0.f; }

#pragma unroll
    for (int kt = 0; kt < 4; kt++){
        int i0 = kt*16 + 2*q, i1 = i0 + 8;
        // even parity (Se)
        {
            float2 f0 = *(const float2*)&Asm[pr0*128 + (i0 ^ sw0)];
            float2 f1 = *(const float2*)&Asm[pr1*128 + (i0 ^ sw1)];
            float2 f2 = *(const float2*)&Asm[pr0*128 + (i1 ^ sw0)];
            float2 f3 = *(const float2*)&Asm[pr1*128 + (i1 ^ sw1)];
            uint32_t ah0 = pack_bf16(f0.x, f0.y), al0 = lo_residual(ah0, f0.x, f0.y);
            uint32_t ah1 = pack_bf16(f1.x, f1.y), al1 = lo_residual(ah1, f1.x, f1.y);
            uint32_t ah2 = pack_bf16(f2.x, f2.y), al2 = lo_residual(ah2, f2.x, f2.y);
            uint32_t ah3 = pack_bf16(f3.x, f3.y), al3 = lo_residual(ah3, f3.x, f3.y);
            int bb = ((wq*4 + kt)*2 + 0)*512 + lane*2;
#pragma unroll
            for (int nt = 0; nt < 8; nt++){
                uint2 bh = *(const uint2*)&TIWH[bb + nt*64];
                uint2 bl = *(const uint2*)&TIWL[bb + nt*64];
                mma16816(accE[nt], ah0, ah1, ah2, ah3, bh.x, bh.y);
                mma16816(accE[nt], ah0, ah1, ah2, ah3, bl.x, bl.y);
                mma16816(accE[nt], al0, al1, al2, al3, bh.x, bh.y);
            }
        }
        // odd parity (So)
        {
            float2 f0 = *(const float2*)&Asm[pr0*128 + 64 + (i0 ^ sw0)];
            float2 f1 = *(const float2*)&Asm[pr1*128 + 64 + (i0 ^ sw1)];
            float2 f2 = *(const float2*)&Asm[pr0*128 + 64 + (i1 ^ sw0)];
            float2 f3 = *(const float2*)&Asm[pr1*128 + 64 + (i1 ^ sw1)];
            uint32_t ah0 = pack_bf16(f0.x, f0.y), al0 = lo_residual(ah0, f0.x, f0.y);
            uint32_t ah1 = pack_bf16(f1.x, f1.y), al1 = lo_residual(ah1, f1.x, f1.y);
            uint32_t ah2 = pack_bf16(f2.x, f2.y), al2 = lo_residual(ah2, f2.x, f2.y);
            uint32_t ah3 = pack_bf16(f3.x, f3.y), al3 = lo_residual(ah3, f3.x, f3.y);
            int bb = ((wq*4 + kt)*2 + 1)*512 + lane*2;
#pragma unroll
            for (int nt = 0; nt < 8; nt++){
                uint2 bh = *(const uint2*)&TIWH[bb + nt*64];
                uint2 bl = *(const uint2*)&TIWL[bb + nt*64];
                mma16816(accO[nt], ah0, ah1, ah2, ah3, bh.x, bh.y);
                mma16816(accO[nt], ah0, ah1, ah2, ah3, bl.x, bl.y);
                mma16816(accO[nt], al0, al1, al2, al3, bh.x, bh.y);
            }
        }
    }
#pragma unroll
    for (int nt = 0; nt < 8; nt++){
        int w = wq*64 + nt*8 + 2*q;
        size_t r0b = ((size_t)ch*Hd + h0 + pr0)*Wd;
        size_t r1b = ((size_t)ch*Hd + h0 + pr1)*Wd;
        *(float2*)&d_s[r0b + w] =
            make_float2(accE[nt][0]+accO[nt][0], accE[nt][1]+accO[nt][1]);
        *(float2*)&d_s[r1b + w] =
            make_float2(accE[nt][2]+accO[nt][2], accE[nt][3]+accO[nt][3]);
        *(float2*)&d_s[r0b + w + 256] =
            make_float2(accE[nt][0]-accO[nt][0], accE[nt][1]-accO[nt][1]);
        *(float2*)&d_s[r1b + w + 256] =
            make_float2(accE[nt][2]-accO[nt][2], accE[nt][3]-accO[nt][3]);
    }
}

// ================= mma.sync bf16 fused residual block v2 =================
#define RT2 2
__global__ void __launch_bounds__(256) k_resid_mma(
        int l,
        const float* __restrict__ b1, const float* __restrict__ b2,
        const float* __restrict__ dw, const float* __restrict__ db,
        float* __restrict__ dout){
    __shared__ float Asm[128*64];

    int tid  = threadIdx.x;
    int lane = tid & 31, wid = tid >> 5;
    int q = lane & 3, r = lane >> 2;

    const uint2* w1h = WBF + ((l*2 + 0)*2 + 0)*1024;
    const uint2* w1l = WBF + ((l*2 + 0)*2 + 1)*1024;
    const uint2* w2h = WBF + ((l*2 + 1)*2 + 0)*1024;
    const uint2* w2l = WBF + ((l*2 + 1)*2 + 1)*1024;

    int wpx = wid * 16;
    int pr0 = wpx + r, pr1 = pr0 + 8;
    int sw0 = (pr0 & 7) << 3, sw1 = (pr1 & 7) << 3;
    float db0 = (dout != nullptr) ? __ldg(db) : 0.f;

    for (int t = 0; t < RT2; t++){
        size_t pbase = ((size_t)blockIdx.x*RT2 + t)*128;
        __syncthreads();
#pragma unroll 8
        for (int c = 0; c < 32; c++){
            int idx = tid + c*256;
            int i = idx >> 7, px = idx & 127;
            Asm[px*64 + (i ^ ((px & 7) << 3))] = d_s[(size_t)i*HW + pbase + px];
        }
        __syncthreads();

        float acc1[8][4];
#pragma unroll
        for (int nt=0; nt<8; nt++)
#pragma unroll
            for (int e=0; e<4; e++) acc1[nt][e] = 0.f;

#pragma unroll
        for (int kt = 0; kt < 4; kt++){
            int i0 = kt*16 + 2*q, i1 = i0 + 8;
            float2 f0 = *(const float2*)&Asm[pr0*64 + (i0 ^ sw0)];
            float2 f1 = *(const float2*)&Asm[pr1*64 + (i0 ^ sw1)];
            float2 f2 = *(const float2*)&Asm[pr0*64 + (i1 ^ sw0)];
            float2 f3 = *(const float2*)&Asm[pr1*64 + (i1 ^ sw1)];
            uint32_t ah0 = pack_bf16(f0.x, f0.y), al0 = lo_residual(ah0, f0.x, f0.y);
            uint32_t ah1 = pack_bf16(f1.x, f1.y), al1 = lo_residual(ah1, f1.x, f1.y);
            uint32_t ah2 = pack_bf16(f2.x, f2.y), al2 = lo_residual(ah2, f2.x, f2.y);
            uint32_t ah3 = pack_bf16(f3.x, f3.y), al3 = lo_residual(ah3, f3.x, f3.y);
#pragma unroll
            for (int nt = 0; nt < 8; nt++){
                int fi = (nt*4 + kt)*32 + lane;
                uint2 bh = __ldg(w1h + fi);
                uint2 bl = __ldg(w1l + fi);
                mma16816(acc1[nt], ah0, ah1, ah2, ah3, bh.x, bh.y);
                mma16816(acc1[nt], ah0, ah1, ah2, ah3, bl.x, bl.y);
                mma16816(acc1[nt], al0, al1, al2, al3, bh.x, bh.y);
            }
        }

        uint32_t a2h[4][4], a2l[4][4];
#pragma unroll
        for (int nt = 0; nt < 8; nt++){
            int j0 = nt*8 + 2*q;
            float bj0 = __ldg(b1 + j0), bj1 = __ldg(b1 + j0 + 1);
            float g0 = gelu_f(acc1[nt][0] + bj0);
            float g1 = gelu_f(acc1[nt][1] + bj1);
            float g2 = gelu_f(acc1[nt][2] + bj0);
            float g3 = gelu_f(acc1[nt][3] + bj1);
            uint32_t h01 = pack_bf16(g0, g1), l01 = lo_residual(h01, g0, g1);
            uint32_t h23 = pack_bf16(g2, g3), l23 = lo_residual(h23, g2, g3);
            int kt = nt >> 1;
            if ((nt & 1) == 0){
                a2h[kt][0] = h01; a2h[kt][1] = h23;
                a2l[kt][0] = l01; a2l[kt][1] = l23;
            } else {
                a2h[kt][2] = h01; a2h[kt][3] = h23;
                a2l[kt][2] = l01; a2l[kt][3] = l23;
            }
        }

        float acc2[8][4];
#pragma unroll
        for (int nt=0; nt<8; nt++)
#pragma unroll
            for (int e=0; e<4; e++) acc2[nt][e] = 0.f;
#pragma unroll
        for (int kt = 0; kt < 4; kt++){
#pragma unroll
            for (int nt = 0; nt < 8; nt++){
                int fi = (nt*4 + kt)*32 + lane;
                uint2 bh = __ldg(w2h + fi);
                uint2 bl = __ldg(w2l + fi);
                mma16816(acc2[nt], a2h[kt][0], a2h[kt][1], a2h[kt][2], a2h[kt][3], bh.x, bh.y);
                mma16816(acc2[nt], a2h[kt][0], a2h[kt][1], a2h[kt][2], a2h[kt][3], bl.x, bl.y);
                mma16816(acc2[nt], a2l[kt][0], a2l[kt][1], a2l[kt][2], a2l[kt][3], bh.x, bh.y);
            }
        }

        size_t p0 = pbase + wpx + r, p1 = p0 + 8;
        float sum0 = 0.f, sum1 = 0.f;
#pragma unroll
        for (int nt = 0; nt < 8; nt++){
            int ch0 = nt*8 + 2*q, ch1 = ch0 + 1;
            float bb0 = __ldg(b2 + ch0), bb1 = __ldg(b2 + ch1);
            float v00 = d_v[(size_t)ch0*HW + p0] + gelu_f(acc2[nt][0] + bb0);
            float v10 = d_v[(size_t)ch1*HW + p0] + gelu_f(acc2[nt][1] + bb1);
            float v01 = d_v[(size_t)ch0*HW + p1] + gelu_f(acc2[nt][2] + bb0);
            float v11 = d_v[(size_t)ch1*HW + p1] + gelu_f(acc2[nt][3] + bb1);
            if (dout == nullptr){
                d_v[(size_t)ch0*HW + p0] = v00;
                d_v[(size_t)ch1*HW + p0] = v10;
                d_v[(size_t)ch0*HW + p1] = v01;
                d_v[(size_t)ch1*HW + p1] = v11;
            } else {
                float w0 = __ldg(dw + ch0), w1 = __ldg(dw + ch1);
                sum0 += w0*v00 + w1*v10;
                sum1 += w0*v01 + w1*v11;
            }
        }
        if (dout != nullptr){
            sum0 += __shfl_xor_sync(0xffffffffu, sum0, 1);
            sum0 += __shfl_xor_sync(0xffffffffu, sum0, 2);
            sum1 += __shfl_xor_sync(0xffffffffu, sum1, 1);
            sum1 += __shfl_xor_sync(0xffffffffu, sum1, 2);
            if (q == 0){
                dout[p0] = sum0 + db0;
                dout[p1] = sum1 + db0;
            }
        }
    }
}

// ---------------- launch ----------------
extern "C" void kernel_launch(void* const* d_in, const int* in_sizes, int n_in,
                              void* d_out, int out_size){
    const float* u    = (const float*)d_in[0];
    const float* x    = (const float*)d_in[1];
    const float* encw = (const float*)d_in[2];
    const float* encb = (const float*)d_in[3];
    const float* decw = (const float*)d_in[4];
    const float* decb = (const float*)d_in[5];
    const float* c1w  = (const float*)d_in[6];
    const float* c1b  = (const float*)d_in[7];
    const float* c2w  = (const float*)d_in[8];
    const float* c2b  = (const float*)d_in[9];
    const float* Are  = (const float*)d_in[10];
    const float* Aim  = (const float*)d_in[11];
    float* out = (float*)d_out;

    k_tables<<<128, 256>>>();
    k_wprep<<<32, 256>>>(c1w, c2w);
    k_enc<<<dim3(HW/256, Cc), 256>>>(u, x, encw, encb);

    for (int l=0; l<Ll; l++){
        k_fwdW<<<dim3(8, Cc), 128>>>();
        k_fwdH<<<dim3(128, 4), 128>>>();
        k_cred<<<1024, 256>>>();
        k_mix<<<dim3(8, Cc), 256>>>(Are + (size_t)l*Cc*Cc*4096,
                                    Aim + (size_t)l*Cc*Cc*4096);
        k_invH<<<dim3(128, 8), 128>>>();
        k_invW<<<dim3(32, Cc), 128>>>();
        bool last = (l == Ll-1);
        k_resid_mma<<<HW/(128*RT2), 256>>>(l, c1b + l*64, c2b + l*64,
                                           last ? decw : nullptr,
                                           last ? decb : nullptr,
                                           last ? out  : nullptr);
    }
}